// round 8
// baseline (speedup 1.0000x reference)
#include <cuda_runtime.h>

// Problem constants
#define NG 4        // bands (G)
#define NB 128      // batch (B)
#define NNODE 30    // nodes (N)
#define NF 5000     // features (F)
#define NC 10       // out channels (C)
#define ROWS_G (NB*NNODE)   // 3840 rows per (mod,g)

// ---------------- device scratch (no allocations allowed) ----------------
__device__ float g_h[3 * NG * ROWS_G * NC];      // h for eeg/emg/cmc
__device__ float g_fused[NG * NB * NNODE * NC];  // fused modality features
__device__ float g_Wt[12 * NC * NF];             // W transposed: [(mod*4+g)*10+c][k]
__device__ float g_cor[NG * NNODE * NNODE];      // mean over T of cmc_train

typedef unsigned long long ull;

// ---------------- f32x2 packed helpers (sm_103a) ----------------
__device__ __forceinline__ ull pack2(float a, float b) {
    ull r;
    unsigned x = __float_as_uint(a), y = __float_as_uint(b);
    asm("mov.b64 %0, {%1, %2};" : "=l"(r) : "r"(x), "r"(y));
    return r;
}
__device__ __forceinline__ ull dup2(float a) {
    ull r;
    unsigned x = __float_as_uint(a);
    asm("mov.b64 %0, {%1, %1};" : "=l"(r) : "r"(x));
    return r;
}
__device__ __forceinline__ void unpack2(ull v, float& lo, float& hi) {
    unsigned x, y;
    asm("mov.b64 {%0, %1}, %2;" : "=r"(x), "=r"(y) : "l"(v));
    lo = __uint_as_float(x); hi = __uint_as_float(y);
}
__device__ __forceinline__ void ffma2(ull& d, ull a, ull b) {
    asm("fma.rn.f32x2 %0, %1, %2, %0;" : "+l"(d) : "l"(a), "l"(b));
}
__device__ __forceinline__ ull add2(ull a, ull b) {
    ull d;
    asm("add.rn.f32x2 %0, %1, %2;" : "=l"(d) : "l"(a), "l"(b));
    return d;
}
__device__ __forceinline__ float warp_max(float v) {
#pragma unroll
    for (int off = 16; off > 0; off >>= 1)
        v = fmaxf(v, __shfl_xor_sync(0xffffffffu, v, off));
    return v;
}
__device__ __forceinline__ float warp_sum(float v) {
#pragma unroll
    for (int off = 16; off > 0; off >>= 1)
        v += __shfl_xor_sync(0xffffffffu, v, off);
    return v;
}

// =====================================================================
// Kernel 0: prep.
// Blocks 0..119: smem-tiled transpose W -> g_Wt (coalesced both ways).
// Blocks 120..123: cor = mean_t cmc_train (per g).
// =====================================================================
__global__ __launch_bounds__(256) void k0_prep(
    const float* __restrict__ Weeg, const float* __restrict__ Wemg,
    const float* __restrict__ Wcmc, const float* __restrict__ cmc_train)
{
    __shared__ float sbuf[5000];
    int blk = blockIdx.x, tid = threadIdx.x;
    if (blk < 120) {
        int mg = blk / 10, chunk = blk % 10;
        int kbase = chunk * 500;
        int mod = mg >> 2, g = mg & 3;
        const float* Wsrc = ((mod == 0) ? Weeg : ((mod == 1) ? Wemg : Wcmc))
                            + (size_t)g * NF * NC + (size_t)kbase * NC;
        for (int i = tid; i < 5000; i += 256) sbuf[i] = Wsrc[i];
        __syncthreads();
        for (int t = tid; t < 5000; t += 256) {
            int c = t / 500, k = t % 500;
            g_Wt[((size_t)mg * NC + c) * NF + kbase + k] = sbuf[k * NC + c];
        }
    } else {
        int g = blk - 120;
        for (int i = tid; i < NNODE * NNODE; i += 256) {
            float s = 0.f;
#pragma unroll
            for (int t = 0; t < 8; t++)
                s += cmc_train[(size_t)t * (NG * NNODE * NNODE)
                               + (size_t)g * (NNODE * NNODE) + i];
            g_cor[g * NNODE * NNODE + i] = s * 0.125f;
        }
    }
}

// =====================================================================
// Kernel 1: h[mod,g,row,c] = sum_k x[row,k] * W[k,c]
// 1440 blocks x 256 threads (8 warps), 2 blocks/SM. Warp owns 4 rows.
// Identical to the proven R4 kernel EXCEPT depth-3 rolling x prefetch
// (3 x 2KB in flight per warp) to cover the ~3800-cycle effective
// memory round trip observed under congestion.
// =====================================================================
#define KT1 1024

__global__ __launch_bounds__(256, 2) void k1_gemm(
    const float* __restrict__ eeg, const float* __restrict__ emg,
    const float* __restrict__ cmc)
{
    __shared__ float Ws[NC][KT1];

    int blk = blockIdx.x;
    int mod = blk / 480;           // 4 g * 120 row-blocks
    int rem = blk % 480;
    int g   = rem / 120;
    int r0  = (rem % 120) * 32;

    const float* x = (mod == 0) ? eeg : ((mod == 1) ? emg : cmc);
    const float* wt = g_Wt + (size_t)(mod * NG + g) * (NC * NF);

    int tid  = threadIdx.x;
    int lane = tid & 31;
    int wid  = tid >> 5;
    int kl   = lane * 4;

    int r0w = r0 + wid * 4;
    const float* q0 = x + ((size_t)g * ROWS_G + r0w) * NF;
    const float* q1 = q0 + NF;
    const float* q2 = q1 + NF;
    const float* q3 = q2 + NF;

    ull a01[NC], a23[NC];
#pragma unroll
    for (int c = 0; c < NC; c++) { a01[c] = 0ull; a23[c] = 0ull; }

    // depth-3 rolling prefetch of x (independent of W tiling)
    float4 xa0 = __ldcs((const float4*)(q0 + kl));
    float4 xa1 = __ldcs((const float4*)(q1 + kl));
    float4 xa2 = __ldcs((const float4*)(q2 + kl));
    float4 xa3 = __ldcs((const float4*)(q3 + kl));
    float4 xb0 = __ldcs((const float4*)(q0 + 128 + kl));
    float4 xb1 = __ldcs((const float4*)(q1 + 128 + kl));
    float4 xb2 = __ldcs((const float4*)(q2 + 128 + kl));
    float4 xb3 = __ldcs((const float4*)(q3 + 128 + kl));
    float4 xc0 = __ldcs((const float4*)(q0 + 256 + kl));
    float4 xc1 = __ldcs((const float4*)(q1 + 256 + kl));
    float4 xc2 = __ldcs((const float4*)(q2 + 256 + kl));
    float4 xc3 = __ldcs((const float4*)(q3 + 256 + kl));
    int knext = 384;               // next k-base to fetch (3 ahead)

#pragma unroll 1
    for (int tile = 0; tile < 5; ++tile) {
        int kbase = tile * KT1;
        int klen  = (NF - kbase < KT1) ? (NF - kbase) : KT1;  // 1024 x4, 904
        if (tile > 0) __syncthreads();      // previous tile fully consumed
        {
            // stage Ws[c][0..klen) from wt[c*NF + kbase ..], float4 coalesced
            int nel4 = (klen * NC) >> 2;    // 2560 or 2260
            int kq   = klen >> 2;           // klen/4
            for (int i4 = tid; i4 < nel4; i4 += 256) {
                int c = i4 / kq, ko = (i4 % kq) << 2;
                *(float4*)&Ws[c][ko] = __ldg((const float4*)(wt + (size_t)c * NF + kbase + ko));
            }
        }
        __syncthreads();

        int nsteps = (tile < 4) ? 8 : 7;    // tile 4: 7*128=896, +8 tail
#pragma unroll 1
        for (int s = 0; s < nsteps; ++s) {
            // pack current head buffer (frees xa regs)
            ull x01x = pack2(xa0.x, xa1.x), x01y = pack2(xa0.y, xa1.y);
            ull x01z = pack2(xa0.z, xa1.z), x01w = pack2(xa0.w, xa1.w);
            ull x23x = pack2(xa2.x, xa3.x), x23y = pack2(xa2.y, xa3.y);
            ull x23z = pack2(xa2.z, xa3.z), x23w = pack2(xa2.w, xa3.w);
            // rotate buffers
            xa0 = xb0; xa1 = xb1; xa2 = xb2; xa3 = xb3;
            xb0 = xc0; xb1 = xc1; xb2 = xc2; xb3 = xc3;
            // refill tail buffer 3 steps ahead
            if (knext <= 4864) {
                xc0 = __ldcs((const float4*)(q0 + knext + kl));
                xc1 = __ldcs((const float4*)(q1 + knext + kl));
                xc2 = __ldcs((const float4*)(q2 + knext + kl));
                xc3 = __ldcs((const float4*)(q3 + knext + kl));
            }
            knext += 128;
            int ks = s * 128 + kl;
#pragma unroll
            for (int c = 0; c < NC; c++) {
                float4 w = *(const float4*)&Ws[c][ks];
                ull wx = dup2(w.x), wy = dup2(w.y), wz = dup2(w.z), ww = dup2(w.w);
                ffma2(a01[c], x01x, wx); ffma2(a01[c], x01y, wy);
                ffma2(a01[c], x01z, wz); ffma2(a01[c], x01w, ww);
                ffma2(a23[c], x23x, wx); ffma2(a23[c], x23y, wy);
                ffma2(a23[c], x23z, wz); ffma2(a23[c], x23w, ww);
            }
        }
    }

    // tail: k = 4992..4999 (tile-4 local offset 896..903), lanes 0..1
    if (lane < 2) {
        int ks = 4992 + kl;
        float4 t0 = __ldcs((const float4*)(q0 + ks));
        float4 t1 = __ldcs((const float4*)(q1 + ks));
        float4 t2 = __ldcs((const float4*)(q2 + ks));
        float4 t3 = __ldcs((const float4*)(q3 + ks));
        ull x01x = pack2(t0.x, t1.x), x01y = pack2(t0.y, t1.y);
        ull x01z = pack2(t0.z, t1.z), x01w = pack2(t0.w, t1.w);
        ull x23x = pack2(t2.x, t3.x), x23y = pack2(t2.y, t3.y);
        ull x23z = pack2(t2.z, t3.z), x23w = pack2(t2.w, t3.w);
#pragma unroll
        for (int c = 0; c < NC; c++) {
            float4 w = *(const float4*)&Ws[c][896 + kl];
            ull wx = dup2(w.x), wy = dup2(w.y), wz = dup2(w.z), ww = dup2(w.w);
            ffma2(a01[c], x01x, wx); ffma2(a01[c], x01y, wy);
            ffma2(a01[c], x01z, wz); ffma2(a01[c], x01w, ww);
            ffma2(a23[c], x23x, wx); ffma2(a23[c], x23y, wy);
            ffma2(a23[c], x23z, wz); ffma2(a23[c], x23w, ww);
        }
    }

    // cross-lane reduction; lo/hi are DIFFERENT rows (no fold)
    size_t outbase = ((size_t)(mod * NG + g) * ROWS_G + r0w) * NC;
#pragma unroll
    for (int c = 0; c < NC; c++) {
        ull v = a01[c];
#pragma unroll
        for (int off = 16; off > 0; off >>= 1)
            v = add2(v, __shfl_down_sync(0xffffffffu, v, off));
        if (lane == 0) {
            float lo, hi; unpack2(v, lo, hi);
            g_h[outbase + c]      = lo;
            g_h[outbase + NC + c] = hi;
        }
        v = a23[c];
#pragma unroll
        for (int off = 16; off > 0; off >>= 1)
            v = add2(v, __shfl_down_sync(0xffffffffu, v, off));
        if (lane == 0) {
            float lo, hi; unpack2(v, lo, hi);
            g_h[outbase + 2 * NC + c] = lo;
            g_h[outbase + 3 * NC + c] = hi;
        }
    }
}

// =====================================================================
// Kernel 2: per (g,b): GAT(eeg), GAT(emg), CMC GCN, modality MoE gate.
// Grid: (128, 4), 128 threads. Warp-parallel softmax (lane = row i),
// warp-per-node gating logits with shuffle reductions.
// =====================================================================
__global__ __launch_bounds__(128) void k2_gat(
    const float* __restrict__ wpli_eeg, const float* __restrict__ wpli_emg,
    const float* __restrict__ a_eeg, const float* __restrict__ a_emg,
    const float* __restrict__ b_cmc,
    const float* __restrict__ g0w1, const float* __restrict__ g0b1,
    const float* __restrict__ g0w2, const float* __restrict__ g0b2)
{
    int b = blockIdx.x, g = blockIdx.y;
    int tid = threadIdx.x;
    int lane = tid & 31;
    int w    = tid >> 5;            // 4 warps

    __shared__ float hX[NNODE][NC];
    __shared__ float fE[NNODE][NC], fM[NNODE][NC], fC[NNODE][NC];
    __shared__ float att[NNODE][32];
    __shared__ float corS[NNODE][NNODE];
    __shared__ float adjS[NNODE * NNODE];
    __shared__ float f1s[NNODE], f2s[NNODE];
    __shared__ float hg[NNODE][64];

    // ---- CMC expert ----
    for (int i = tid; i < NNODE * NNODE; i += 128)
        corS[i / NNODE][i % NNODE] = g_cor[g * NNODE * NNODE + i];
    {
        size_t hb = ((size_t)(2 * NG + g) * ROWS_G + (size_t)b * NNODE) * NC;
        for (int i = tid; i < NNODE * NC; i += 128)
            hX[i / NC][i % NC] = g_h[hb + i];
    }
    __syncthreads();
    for (int idx = tid; idx < NNODE * NC; idx += 128) {
        int i = idx / NC, c = idx % NC;
        float s = 0.f;
        for (int j = 0; j < NNODE; j++) s += corS[i][j] * hX[j][c];
        fC[i][c] = s + b_cmc[g * NC + c];
    }
    __syncthreads();

    // ---- GAT experts (eeg, emg) ----
    for (int m = 0; m < 2; ++m) {
        const float* a   = ((m == 0) ? a_eeg : a_emg) + g * 2 * NC;
        const float* adj = ((m == 0) ? wpli_eeg : wpli_emg) + g * NNODE * NNODE;
        size_t hb = ((size_t)(m * NG + g) * ROWS_G + (size_t)b * NNODE) * NC;
        for (int i = tid; i < NNODE * NC; i += 128)
            hX[i / NC][i % NC] = g_h[hb + i];
        for (int i = tid; i < NNODE * NNODE; i += 128)
            adjS[i] = adj[i];
        __syncthreads();
        if (tid < NNODE) {
            float s1 = 0.f, s2 = 0.f;
#pragma unroll
            for (int c = 0; c < NC; c++) {
                s1 += hX[tid][c] * a[c];
                s2 += hX[tid][c] * a[NC + c];
            }
            f1s[tid] = s1; f2s[tid] = s2;
        }
        __syncthreads();
        // warp-parallel softmax over i for each column j (warp w: j = w+4jj)
        {
            int i = lane;
#pragma unroll 1
            for (int jj = 0; jj < 8; ++jj) {
                int j = w + 4 * jj;
                if (j >= NNODE) break;
                float v = -1e30f;
                if (i < NNODE) {
                    if (adjS[i * NNODE + j] > 0.f) {
                        float e = f1s[i] + f2s[j];
                        v = (e > 0.f) ? e : 0.1f * e;   // LeakyReLU(0.1)
                    } else {
                        v = -1e12f;
                    }
                }
                float mx = warp_max(v);
                float ex = (i < NNODE) ? expf(v - mx) : 0.f;
                float sm = warp_sum(ex);
                if (i < NNODE) att[i][j] = ex / sm;
            }
        }
        __syncthreads();
        for (int idx = tid; idx < NNODE * NC; idx += 128) {
            int i = idx / NC, c = idx % NC;
            float s = 0.f;
            for (int j = 0; j < NNODE; j++) s += att[i][j] * hX[j][c];
            float r = fmaxf(s, 0.f);
            if (m == 0) fE[i][c] = r; else fM[i][c] = r;
        }
        __syncthreads();
    }

    // ---- gating0 hidden layer: hg[n][o] ----
    for (int idx = tid; idx < NNODE * 64; idx += 128) {
        int n = idx / 64, o = idx % 64;
        float s = g0b1[o];
#pragma unroll
        for (int k = 0; k < 10; k++) s += fE[n][k] * g0w1[k * 64 + o];
#pragma unroll
        for (int k = 0; k < 10; k++) s += fM[n][k] * g0w1[(10 + k) * 64 + o];
#pragma unroll
        for (int k = 0; k < 10; k++) s += fC[n][k] * g0w1[(20 + k) * 64 + o];
        hg[n][o] = fmaxf(s, 0.f);
    }
    __syncthreads();

    // ---- gating0 logits + softmax + fuse: warp per node ----
#pragma unroll 1
    for (int jj = 0; jj < 8; ++jj) {
        int n = w + 4 * jj;
        if (n >= NNODE) break;
        float v0 = hg[n][lane], v1 = hg[n][lane + 32];
        float l0 = v0 * g0w2[lane * 3 + 0] + v1 * g0w2[(lane + 32) * 3 + 0];
        float l1 = v0 * g0w2[lane * 3 + 1] + v1 * g0w2[(lane + 32) * 3 + 1];
        float l2 = v0 * g0w2[lane * 3 + 2] + v1 * g0w2[(lane + 32) * 3 + 2];
        l0 = warp_sum(l0); l1 = warp_sum(l1); l2 = warp_sum(l2);
        l0 += g0b2[0]; l1 += g0b2[1]; l2 += g0b2[2];
        float mx = fmaxf(l0, fmaxf(l1, l2));
        float e0 = expf(l0 - mx), e1 = expf(l1 - mx), e2 = expf(l2 - mx);
        float inv = 1.f / (e0 + e1 + e2);
        e0 *= inv; e1 *= inv; e2 *= inv;
        if (lane < NC) {
            size_t ob = ((size_t)(g * NB + b) * NNODE + n) * NC + lane;
            g_fused[ob] = e0 * fE[n][lane] + e1 * fM[n][lane] + e2 * fC[n][lane];
        }
    }
}

// =====================================================================
// Kernel 3: per b: band MoE gate, node pooling, MLP head + BN
// Grid: 128 blocks, 256 threads.
// =====================================================================
__global__ __launch_bounds__(256) void k3_head(
    const float* __restrict__ g1w1, const float* __restrict__ g1b1,
    const float* __restrict__ g1w2, const float* __restrict__ g1b2,
    const float* __restrict__ mlp0w, const float* __restrict__ mlp0b,
    const float* __restrict__ mlp1w, const float* __restrict__ mlp1b,
    const float* __restrict__ mlp2w, const float* __restrict__ mlp2b,
    const float* __restrict__ bng, const float* __restrict__ bnb,
    float* __restrict__ out)
{
    int b = blockIdx.x, tid = threadIdx.x;
    int lane = tid & 31;
    int w    = tid >> 5;            // 8 warps
    __shared__ float band[NNODE][40];
    __shared__ float hg[NNODE][64];
    __shared__ float gs[NNODE][4];
    __shared__ float pool[6][40];
    __shared__ float feat[40];
    __shared__ float h1[256];
    __shared__ float p1[8][32];
    __shared__ float h2[32];

    for (int idx = tid; idx < NNODE * 40; idx += 256) {
        int n = idx / 40, d = idx % 40, g = d / 10, c = d % 10;
        band[n][d] = g_fused[((size_t)(g * NB + b) * NNODE + n) * NC + c];
    }
    __syncthreads();

    for (int idx = tid; idx < NNODE * 64; idx += 256) {
        int n = idx / 64, o = idx % 64;
        float s = g1b1[o];
#pragma unroll
        for (int k = 0; k < 40; k++) s += band[n][k] * g1w1[k * 64 + o];
        hg[n][o] = fmaxf(s, 0.f);
    }
    __syncthreads();

    // band-gate logits: warp per node, lanes over 64 hidden (2 each)
#pragma unroll 1
    for (int jj = 0; jj < 4; ++jj) {
        int n = w + 8 * jj;
        if (n >= NNODE) break;
        float v0 = hg[n][lane], v1 = hg[n][lane + 32];
        float l[4];
#pragma unroll
        for (int e = 0; e < 4; e++)
            l[e] = v0 * g1w2[lane * 4 + e] + v1 * g1w2[(lane + 32) * 4 + e];
#pragma unroll
        for (int e = 0; e < 4; e++) l[e] = warp_sum(l[e]);
        if (lane == 0) {
#pragma unroll
            for (int e = 0; e < 4; e++) l[e] += g1b2[e];
            float mx = fmaxf(fmaxf(l[0], l[1]), fmaxf(l[2], l[3]));
            float s = 0.f;
#pragma unroll
            for (int e = 0; e < 4; e++) { l[e] = expf(l[e] - mx); s += l[e]; }
            float inv = 1.f / s;
#pragma unroll
            for (int e = 0; e < 4; e++) gs[n][e] = l[e] * inv;
        }
    }
    __syncthreads();

    // pooling: 240 threads = 40 d x 6 node-chunks of 5
    if (tid < 240) {
        int d = tid % 40, ch = tid / 40;
        float s = 0.f;
#pragma unroll
        for (int nn = 0; nn < 5; nn++) {
            int n = ch * 5 + nn;
            s += band[n][d] * gs[n][d / 10];
        }
        pool[ch][d] = s;
    }
    __syncthreads();
    if (tid < 40) {
        float s = 0.f;
#pragma unroll
        for (int ch = 0; ch < 6; ch++) s += pool[ch][tid];
        feat[tid] = s * (1.f / 30.f);
    }
    __syncthreads();

    {
        int o = tid;
        float s = mlp0b[o];
#pragma unroll
        for (int k = 0; k < 40; k++) s += feat[k] * mlp0w[k * 256 + o];
        h1[o] = fmaxf(s, 0.f);
    }
    __syncthreads();
    {
        // mlp1: 256 -> 32, parallelized over (slice, o)
        int o = tid & 31, sl = tid >> 5;
        float s = 0.f;
#pragma unroll
        for (int ki = 0; ki < 32; ki++) {
            int k = sl * 32 + ki;
            s += h1[k] * mlp1w[k * 32 + o];
        }
        p1[sl][o] = s;
    }
    __syncthreads();
    if (tid < 32) {
        float s = mlp1b[tid];
#pragma unroll
        for (int j = 0; j < 8; j++) s += p1[j][tid];
        s = fmaxf(s, 0.f);
        h2[tid] = s * (bng[tid] * rsqrtf(1.f + 1e-5f)) + bnb[tid];
    }
    __syncthreads();
    if (tid < 128) {
        int e = w;                   // warps 0..3, one output each
        float s = h2[lane] * mlp2w[lane * 4 + e];
        s = warp_sum(s);
        if (lane == 0) out[b * 4 + e] = s + mlp2b[e];
    }
}

// =====================================================================
extern "C" void kernel_launch(void* const* d_in, const int* in_sizes, int n_in,
                              void* d_out, int out_size)
{
    const float* eeg       = (const float*)d_in[0];
    const float* wpli_eeg  = (const float*)d_in[1];
    const float* emg       = (const float*)d_in[2];
    const float* wpli_emg  = (const float*)d_in[3];
    const float* cmc       = (const float*)d_in[4];
    const float* cmc_train = (const float*)d_in[5];
    const float* W_eeg     = (const float*)d_in[6];
    const float* a_eeg     = (const float*)d_in[7];
    const float* W_emg     = (const float*)d_in[8];
    const float* a_emg     = (const float*)d_in[9];
    const float* W_cmc     = (const float*)d_in[10];
    const float* b_cmc     = (const float*)d_in[11];
    const float* g0w1      = (const float*)d_in[12];
    const float* g0b1      = (const float*)d_in[13];
    const float* g0w2      = (const float*)d_in[14];
    const float* g0b2      = (const float*)d_in[15];
    const float* g1w1      = (const float*)d_in[16];
    const float* g1b1      = (const float*)d_in[17];
    const float* g1w2      = (const float*)d_in[18];
    const float* g1b2      = (const float*)d_in[19];
    const float* mlp0w     = (const float*)d_in[20];
    const float* mlp0b     = (const float*)d_in[21];
    const float* mlp1w     = (const float*)d_in[22];
    const float* mlp1b     = (const float*)d_in[23];
    const float* mlp2w     = (const float*)d_in[24];
    const float* mlp2b     = (const float*)d_in[25];
    const float* bng       = (const float*)d_in[26];
    const float* bnb       = (const float*)d_in[27];

    k0_prep<<<124, 256>>>(W_eeg, W_emg, W_cmc, cmc_train);

    k1_gemm<<<1440, 256>>>(eeg, emg, cmc);

    dim3 g2(NB, NG);
    k2_gat<<<g2, 128>>>(wpli_eeg, wpli_emg, a_eeg, a_emg, b_cmc,
                        g0w1, g0b1, g0w2, g0b2);

    k3_head<<<NB, 256>>>(g1w1, g1b1, g1w2, g1b2,
                         mlp0w, mlp0b, mlp1w, mlp1b, mlp2w, mlp2b,
                         bng, bnb, (float*)d_out);
}

// round 9
// speedup vs baseline: 1.1090x; 1.1090x over previous
#include <cuda_runtime.h>

// Problem constants
#define NG 4        // bands (G)
#define NB 128      // batch (B)
#define NNODE 30    // nodes (N)
#define NF 5000     // features (F)
#define NC 10       // out channels (C)
#define ROWS_G (NB*NNODE)   // 3840 rows per (mod,g)

// ---------------- device scratch (no allocations allowed) ----------------
__device__ float g_h[3 * NG * ROWS_G * NC];      // h for eeg/emg/cmc
__device__ float g_fused[NG * NB * NNODE * NC];  // fused modality features
__device__ float g_Wt[12 * NC * NF];             // W transposed: [(mod*4+g)*10+c][k]
__device__ float g_cor[NG * NNODE * NNODE];      // mean over T of cmc_train

typedef unsigned long long ull;

// ---------------- f32x2 packed helpers (sm_103a) ----------------
__device__ __forceinline__ ull pack2(float a, float b) {
    ull r;
    unsigned x = __float_as_uint(a), y = __float_as_uint(b);
    asm("mov.b64 %0, {%1, %2};" : "=l"(r) : "r"(x), "r"(y));
    return r;
}
__device__ __forceinline__ ull dup2(float a) {
    ull r;
    unsigned x = __float_as_uint(a);
    asm("mov.b64 %0, {%1, %1};" : "=l"(r) : "r"(x));
    return r;
}
__device__ __forceinline__ void unpack2(ull v, float& lo, float& hi) {
    unsigned x, y;
    asm("mov.b64 {%0, %1}, %2;" : "=r"(x), "=r"(y) : "l"(v));
    lo = __uint_as_float(x); hi = __uint_as_float(y);
}
__device__ __forceinline__ void ffma2(ull& d, ull a, ull b) {
    asm("fma.rn.f32x2 %0, %1, %2, %0;" : "+l"(d) : "l"(a), "l"(b));
}
__device__ __forceinline__ ull add2(ull a, ull b) {
    ull d;
    asm("add.rn.f32x2 %0, %1, %2;" : "=l"(d) : "l"(a), "l"(b));
    return d;
}
__device__ __forceinline__ float warp_max(float v) {
#pragma unroll
    for (int off = 16; off > 0; off >>= 1)
        v = fmaxf(v, __shfl_xor_sync(0xffffffffu, v, off));
    return v;
}
__device__ __forceinline__ float warp_sum(float v) {
#pragma unroll
    for (int off = 16; off > 0; off >>= 1)
        v += __shfl_xor_sync(0xffffffffu, v, off);
    return v;
}

// =====================================================================
// Kernel 0: prep.
// Blocks 0..119: smem-tiled transpose W -> g_Wt (coalesced both ways).
// Blocks 120..123: cor = mean_t cmc_train (per g).
// =====================================================================
__global__ __launch_bounds__(256) void k0_prep(
    const float* __restrict__ Weeg, const float* __restrict__ Wemg,
    const float* __restrict__ Wcmc, const float* __restrict__ cmc_train)
{
    __shared__ float sbuf[5000];
    int blk = blockIdx.x, tid = threadIdx.x;
    if (blk < 120) {
        int mg = blk / 10, chunk = blk % 10;
        int kbase = chunk * 500;
        int mod = mg >> 2, g = mg & 3;
        const float* Wsrc = ((mod == 0) ? Weeg : ((mod == 1) ? Wemg : Wcmc))
                            + (size_t)g * NF * NC + (size_t)kbase * NC;
        for (int i = tid; i < 5000; i += 256) sbuf[i] = Wsrc[i];
        __syncthreads();
        for (int t = tid; t < 5000; t += 256) {
            int c = t / 500, k = t % 500;
            g_Wt[((size_t)mg * NC + c) * NF + kbase + k] = sbuf[k * NC + c];
        }
    } else {
        int g = blk - 120;
        for (int i = tid; i < NNODE * NNODE; i += 256) {
            float s = 0.f;
#pragma unroll
            for (int t = 0; t < 8; t++)
                s += cmc_train[(size_t)t * (NG * NNODE * NNODE)
                               + (size_t)g * (NNODE * NNODE) + i];
            g_cor[g * NNODE * NNODE + i] = s * 0.125f;
        }
    }
}

// =====================================================================
// Kernel 1: h[mod,g,row,c] = sum_k x[row,k] * W[k,c]
// EXACT revert to the Round-3 kernel (fastest k1 measured, ~186us):
// 2880 blocks x 128 threads, no smem, no syncs, 4 blocks/SM.
// Warp owns 4 rows. Row-pair f32x2 accumulators (40 regs). x streamed
// via __ldcs; W via __ldg from pre-transposed g_Wt. Depth-2 prefetch.
// =====================================================================
__global__ __launch_bounds__(128, 4) void k1_gemm(
    const float* __restrict__ eeg, const float* __restrict__ emg,
    const float* __restrict__ cmc)
{
    int blk = blockIdx.x;
    int mod = blk / 960;           // 4 g * 240 row-blocks
    int rem = blk % 960;
    int g   = rem / 240;
    int r0  = (rem % 240) * 16;

    const float* x = (mod == 0) ? eeg : ((mod == 1) ? emg : cmc);

    int tid  = threadIdx.x;
    int lane = tid & 31;
    int wid  = tid >> 5;
    int kl   = lane * 4;

    int r0w = r0 + wid * 4;
    const float* q0 = x + ((size_t)g * ROWS_G + r0w) * NF;
    const float* q1 = q0 + NF;
    const float* q2 = q1 + NF;
    const float* q3 = q2 + NF;
    const float* wp = g_Wt + (size_t)(mod * NG + g) * (NC * NF) + kl;

    ull a01[NC], a23[NC];
#pragma unroll
    for (int c = 0; c < NC; c++) { a01[c] = 0ull; a23[c] = 0ull; }

    // depth-2 rolling prefetch
    float4 xa0 = __ldcs((const float4*)(q0 + kl));
    float4 xa1 = __ldcs((const float4*)(q1 + kl));
    float4 xa2 = __ldcs((const float4*)(q2 + kl));
    float4 xa3 = __ldcs((const float4*)(q3 + kl));
    float4 xb0 = __ldcs((const float4*)(q0 + 128 + kl));
    float4 xb1 = __ldcs((const float4*)(q1 + 128 + kl));
    float4 xb2 = __ldcs((const float4*)(q2 + 128 + kl));
    float4 xb3 = __ldcs((const float4*)(q3 + 128 + kl));

#pragma unroll 3
    for (int s = 0; s < 39; ++s) {      // 39*128 = 4992 k
        float4 xc0, xc1, xc2, xc3;
        if (s < 37) {
            int kn = (s + 2) * 128 + kl;
            xc0 = __ldcs((const float4*)(q0 + kn));
            xc1 = __ldcs((const float4*)(q1 + kn));
            xc2 = __ldcs((const float4*)(q2 + kn));
            xc3 = __ldcs((const float4*)(q3 + kn));
        }
        // pack x across row-pairs (rows 0,1) and (2,3)
        ull x01x = pack2(xa0.x, xa1.x), x01y = pack2(xa0.y, xa1.y);
        ull x01z = pack2(xa0.z, xa1.z), x01w = pack2(xa0.w, xa1.w);
        ull x23x = pack2(xa2.x, xa3.x), x23y = pack2(xa2.y, xa3.y);
        ull x23z = pack2(xa2.z, xa3.z), x23w = pack2(xa2.w, xa3.w);
        int ks = s * 128;
#pragma unroll
        for (int c = 0; c < NC; c++) {
            float4 w = __ldg((const float4*)(wp + (size_t)c * NF + ks));
            ull wx = dup2(w.x), wy = dup2(w.y), wz = dup2(w.z), ww = dup2(w.w);
            ffma2(a01[c], x01x, wx); ffma2(a01[c], x01y, wy);
            ffma2(a01[c], x01z, wz); ffma2(a01[c], x01w, ww);
            ffma2(a23[c], x23x, wx); ffma2(a23[c], x23y, wy);
            ffma2(a23[c], x23z, wz); ffma2(a23[c], x23w, ww);
        }
        xa0 = xb0; xa1 = xb1; xa2 = xb2; xa3 = xb3;
        xb0 = xc0; xb1 = xc1; xb2 = xc2; xb3 = xc3;
    }

    // tail: k = 4992..4999 (2 float4s), lanes 0..1
    if (lane < 2) {
        int ks = 4992 + kl;
        float4 x0 = __ldcs((const float4*)(q0 + ks));
        float4 x1 = __ldcs((const float4*)(q1 + ks));
        float4 x2 = __ldcs((const float4*)(q2 + ks));
        float4 x3 = __ldcs((const float4*)(q3 + ks));
        ull x01x = pack2(x0.x, x1.x), x01y = pack2(x0.y, x1.y);
        ull x01z = pack2(x0.z, x1.z), x01w = pack2(x0.w, x1.w);
        ull x23x = pack2(x2.x, x3.x), x23y = pack2(x2.y, x3.y);
        ull x23z = pack2(x2.z, x3.z), x23w = pack2(x2.w, x3.w);
#pragma unroll
        for (int c = 0; c < NC; c++) {
            float4 w = __ldg((const float4*)(wp + (size_t)c * NF + 4992));
            ull wx = dup2(w.x), wy = dup2(w.y), wz = dup2(w.z), ww = dup2(w.w);
            ffma2(a01[c], x01x, wx); ffma2(a01[c], x01y, wy);
            ffma2(a01[c], x01z, wz); ffma2(a01[c], x01w, ww);
            ffma2(a23[c], x23x, wx); ffma2(a23[c], x23y, wy);
            ffma2(a23[c], x23z, wz); ffma2(a23[c], x23w, ww);
        }
    }

    // cross-lane reduction; lo/hi are DIFFERENT rows (no fold)
    size_t outbase = ((size_t)(mod * NG + g) * ROWS_G + r0w) * NC;
#pragma unroll
    for (int c = 0; c < NC; c++) {
        ull v = a01[c];
#pragma unroll
        for (int off = 16; off > 0; off >>= 1)
            v = add2(v, __shfl_down_sync(0xffffffffu, v, off));
        if (lane == 0) {
            float lo, hi; unpack2(v, lo, hi);
            g_h[outbase + c]      = lo;
            g_h[outbase + NC + c] = hi;
        }
        v = a23[c];
#pragma unroll
        for (int off = 16; off > 0; off >>= 1)
            v = add2(v, __shfl_down_sync(0xffffffffu, v, off));
        if (lane == 0) {
            float lo, hi; unpack2(v, lo, hi);
            g_h[outbase + 2 * NC + c] = lo;
            g_h[outbase + 3 * NC + c] = hi;
        }
    }
}

// =====================================================================
// Kernel 2: per (g,b): GAT(eeg), GAT(emg), CMC GCN, modality MoE gate.
// Grid: (128, 4), 128 threads. Warp-parallel softmax (lane = row i),
// warp-per-node gating logits with shuffle reductions.
// =====================================================================
__global__ __launch_bounds__(128) void k2_gat(
    const float* __restrict__ wpli_eeg, const float* __restrict__ wpli_emg,
    const float* __restrict__ a_eeg, const float* __restrict__ a_emg,
    const float* __restrict__ b_cmc,
    const float* __restrict__ g0w1, const float* __restrict__ g0b1,
    const float* __restrict__ g0w2, const float* __restrict__ g0b2)
{
    int b = blockIdx.x, g = blockIdx.y;
    int tid = threadIdx.x;
    int lane = tid & 31;
    int w    = tid >> 5;            // 4 warps

    __shared__ float hX[NNODE][NC];
    __shared__ float fE[NNODE][NC], fM[NNODE][NC], fC[NNODE][NC];
    __shared__ float att[NNODE][32];
    __shared__ float corS[NNODE][NNODE];
    __shared__ float adjS[NNODE * NNODE];
    __shared__ float f1s[NNODE], f2s[NNODE];
    __shared__ float hg[NNODE][64];

    // ---- CMC expert ----
    for (int i = tid; i < NNODE * NNODE; i += 128)
        corS[i / NNODE][i % NNODE] = g_cor[g * NNODE * NNODE + i];
    {
        size_t hb = ((size_t)(2 * NG + g) * ROWS_G + (size_t)b * NNODE) * NC;
        for (int i = tid; i < NNODE * NC; i += 128)
            hX[i / NC][i % NC] = g_h[hb + i];
    }
    __syncthreads();
    for (int idx = tid; idx < NNODE * NC; idx += 128) {
        int i = idx / NC, c = idx % NC;
        float s = 0.f;
        for (int j = 0; j < NNODE; j++) s += corS[i][j] * hX[j][c];
        fC[i][c] = s + b_cmc[g * NC + c];
    }
    __syncthreads();

    // ---- GAT experts (eeg, emg) ----
    for (int m = 0; m < 2; ++m) {
        const float* a   = ((m == 0) ? a_eeg : a_emg) + g * 2 * NC;
        const float* adj = ((m == 0) ? wpli_eeg : wpli_emg) + g * NNODE * NNODE;
        size_t hb = ((size_t)(m * NG + g) * ROWS_G + (size_t)b * NNODE) * NC;
        for (int i = tid; i < NNODE * NC; i += 128)
            hX[i / NC][i % NC] = g_h[hb + i];
        for (int i = tid; i < NNODE * NNODE; i += 128)
            adjS[i] = adj[i];
        __syncthreads();
        if (tid < NNODE) {
            float s1 = 0.f, s2 = 0.f;
#pragma unroll
            for (int c = 0; c < NC; c++) {
                s1 += hX[tid][c] * a[c];
                s2 += hX[tid][c] * a[NC + c];
            }
            f1s[tid] = s1; f2s[tid] = s2;
        }
        __syncthreads();
        // warp-parallel softmax over i for each column j (warp w: j = w+4jj)
        {
            int i = lane;
#pragma unroll 1
            for (int jj = 0; jj < 8; ++jj) {
                int j = w + 4 * jj;
                if (j >= NNODE) break;
                float v = -1e30f;
                if (i < NNODE) {
                    if (adjS[i * NNODE + j] > 0.f) {
                        float e = f1s[i] + f2s[j];
                        v = (e > 0.f) ? e : 0.1f * e;   // LeakyReLU(0.1)
                    } else {
                        v = -1e12f;
                    }
                }
                float mx = warp_max(v);
                float ex = (i < NNODE) ? expf(v - mx) : 0.f;
                float sm = warp_sum(ex);
                if (i < NNODE) att[i][j] = ex / sm;
            }
        }
        __syncthreads();
        for (int idx = tid; idx < NNODE * NC; idx += 128) {
            int i = idx / NC, c = idx % NC;
            float s = 0.f;
            for (int j = 0; j < NNODE; j++) s += att[i][j] * hX[j][c];
            float r = fmaxf(s, 0.f);
            if (m == 0) fE[i][c] = r; else fM[i][c] = r;
        }
        __syncthreads();
    }

    // ---- gating0 hidden layer: hg[n][o] ----
    for (int idx = tid; idx < NNODE * 64; idx += 128) {
        int n = idx / 64, o = idx % 64;
        float s = g0b1[o];
#pragma unroll
        for (int k = 0; k < 10; k++) s += fE[n][k] * g0w1[k * 64 + o];
#pragma unroll
        for (int k = 0; k < 10; k++) s += fM[n][k] * g0w1[(10 + k) * 64 + o];
#pragma unroll
        for (int k = 0; k < 10; k++) s += fC[n][k] * g0w1[(20 + k) * 64 + o];
        hg[n][o] = fmaxf(s, 0.f);
    }
    __syncthreads();

    // ---- gating0 logits + softmax + fuse: warp per node ----
#pragma unroll 1
    for (int jj = 0; jj < 8; ++jj) {
        int n = w + 4 * jj;
        if (n >= NNODE) break;
        float v0 = hg[n][lane], v1 = hg[n][lane + 32];
        float l0 = v0 * g0w2[lane * 3 + 0] + v1 * g0w2[(lane + 32) * 3 + 0];
        float l1 = v0 * g0w2[lane * 3 + 1] + v1 * g0w2[(lane + 32) * 3 + 1];
        float l2 = v0 * g0w2[lane * 3 + 2] + v1 * g0w2[(lane + 32) * 3 + 2];
        l0 = warp_sum(l0); l1 = warp_sum(l1); l2 = warp_sum(l2);
        l0 += g0b2[0]; l1 += g0b2[1]; l2 += g0b2[2];
        float mx = fmaxf(l0, fmaxf(l1, l2));
        float e0 = expf(l0 - mx), e1 = expf(l1 - mx), e2 = expf(l2 - mx);
        float inv = 1.f / (e0 + e1 + e2);
        e0 *= inv; e1 *= inv; e2 *= inv;
        if (lane < NC) {
            size_t ob = ((size_t)(g * NB + b) * NNODE + n) * NC + lane;
            g_fused[ob] = e0 * fE[n][lane] + e1 * fM[n][lane] + e2 * fC[n][lane];
        }
    }
}

// =====================================================================
// Kernel 3: per b: band MoE gate, node pooling, MLP head + BN
// Grid: 128 blocks, 256 threads.
// =====================================================================
__global__ __launch_bounds__(256) void k3_head(
    const float* __restrict__ g1w1, const float* __restrict__ g1b1,
    const float* __restrict__ g1w2, const float* __restrict__ g1b2,
    const float* __restrict__ mlp0w, const float* __restrict__ mlp0b,
    const float* __restrict__ mlp1w, const float* __restrict__ mlp1b,
    const float* __restrict__ mlp2w, const float* __restrict__ mlp2b,
    const float* __restrict__ bng, const float* __restrict__ bnb,
    float* __restrict__ out)
{
    int b = blockIdx.x, tid = threadIdx.x;
    int lane = tid & 31;
    int w    = tid >> 5;            // 8 warps
    __shared__ float band[NNODE][40];
    __shared__ float hg[NNODE][64];
    __shared__ float gs[NNODE][4];
    __shared__ float pool[6][40];
    __shared__ float feat[40];
    __shared__ float h1[256];
    __shared__ float p1[8][32];
    __shared__ float h2[32];

    for (int idx = tid; idx < NNODE * 40; idx += 256) {
        int n = idx / 40, d = idx % 40, g = d / 10, c = d % 10;
        band[n][d] = g_fused[((size_t)(g * NB + b) * NNODE + n) * NC + c];
    }
    __syncthreads();

    for (int idx = tid; idx < NNODE * 64; idx += 256) {
        int n = idx / 64, o = idx % 64;
        float s = g1b1[o];
#pragma unroll
        for (int k = 0; k < 40; k++) s += band[n][k] * g1w1[k * 64 + o];
        hg[n][o] = fmaxf(s, 0.f);
    }
    __syncthreads();

    // band-gate logits: warp per node, lanes over 64 hidden (2 each)
#pragma unroll 1
    for (int jj = 0; jj < 4; ++jj) {
        int n = w + 8 * jj;
        if (n >= NNODE) break;
        float v0 = hg[n][lane], v1 = hg[n][lane + 32];
        float l[4];
#pragma unroll
        for (int e = 0; e < 4; e++)
            l[e] = v0 * g1w2[lane * 4 + e] + v1 * g1w2[(lane + 32) * 4 + e];
#pragma unroll
        for (int e = 0; e < 4; e++) l[e] = warp_sum(l[e]);
        if (lane == 0) {
#pragma unroll
            for (int e = 0; e < 4; e++) l[e] += g1b2[e];
            float mx = fmaxf(fmaxf(l[0], l[1]), fmaxf(l[2], l[3]));
            float s = 0.f;
#pragma unroll
            for (int e = 0; e < 4; e++) { l[e] = expf(l[e] - mx); s += l[e]; }
            float inv = 1.f / s;
#pragma unroll
            for (int e = 0; e < 4; e++) gs[n][e] = l[e] * inv;
        }
    }
    __syncthreads();

    // pooling: 240 threads = 40 d x 6 node-chunks of 5
    if (tid < 240) {
        int d = tid % 40, ch = tid / 40;
        float s = 0.f;
#pragma unroll
        for (int nn = 0; nn < 5; nn++) {
            int n = ch * 5 + nn;
            s += band[n][d] * gs[n][d / 10];
        }
        pool[ch][d] = s;
    }
    __syncthreads();
    if (tid < 40) {
        float s = 0.f;
#pragma unroll
        for (int ch = 0; ch < 6; ch++) s += pool[ch][tid];
        feat[tid] = s * (1.f / 30.f);
    }
    __syncthreads();

    {
        int o = tid;
        float s = mlp0b[o];
#pragma unroll
        for (int k = 0; k < 40; k++) s += feat[k] * mlp0w[k * 256 + o];
        h1[o] = fmaxf(s, 0.f);
    }
    __syncthreads();
    {
        // mlp1: 256 -> 32, parallelized over (slice, o)
        int o = tid & 31, sl = tid >> 5;
        float s = 0.f;
#pragma unroll
        for (int ki = 0; ki < 32; ki++) {
            int k = sl * 32 + ki;
            s += h1[k] * mlp1w[k * 32 + o];
        }
        p1[sl][o] = s;
    }
    __syncthreads();
    if (tid < 32) {
        float s = mlp1b[tid];
#pragma unroll
        for (int j = 0; j < 8; j++) s += p1[j][tid];
        s = fmaxf(s, 0.f);
        h2[tid] = s * (bng[tid] * rsqrtf(1.f + 1e-5f)) + bnb[tid];
    }
    __syncthreads();
    if (tid < 128) {
        int e = w;                   // warps 0..3, one output each
        float s = h2[lane] * mlp2w[lane * 4 + e];
        s = warp_sum(s);
        if (lane == 0) out[b * 4 + e] = s + mlp2b[e];
    }
}

// =====================================================================
extern "C" void kernel_launch(void* const* d_in, const int* in_sizes, int n_in,
                              void* d_out, int out_size)
{
    const float* eeg       = (const float*)d_in[0];
    const float* wpli_eeg  = (const float*)d_in[1];
    const float* emg       = (const float*)d_in[2];
    const float* wpli_emg  = (const float*)d_in[3];
    const float* cmc       = (const float*)d_in[4];
    const float* cmc_train = (const float*)d_in[5];
    const float* W_eeg     = (const float*)d_in[6];
    const float* a_eeg     = (const float*)d_in[7];
    const float* W_emg     = (const float*)d_in[8];
    const float* a_emg     = (const float*)d_in[9];
    const float* W_cmc     = (const float*)d_in[10];
    const float* b_cmc     = (const float*)d_in[11];
    const float* g0w1      = (const float*)d_in[12];
    const float* g0b1      = (const float*)d_in[13];
    const float* g0w2      = (const float*)d_in[14];
    const float* g0b2      = (const float*)d_in[15];
    const float* g1w1      = (const float*)d_in[16];
    const float* g1b1      = (const float*)d_in[17];
    const float* g1w2      = (const float*)d_in[18];
    const float* g1b2      = (const float*)d_in[19];
    const float* mlp0w     = (const float*)d_in[20];
    const float* mlp0b     = (const float*)d_in[21];
    const float* mlp1w     = (const float*)d_in[22];
    const float* mlp1b     = (const float*)d_in[23];
    const float* mlp2w     = (const float*)d_in[24];
    const float* mlp2b     = (const float*)d_in[25];
    const float* bng       = (const float*)d_in[26];
    const float* bnb       = (const float*)d_in[27];

    k0_prep<<<124, 256>>>(W_eeg, W_emg, W_cmc, cmc_train);

    k1_gemm<<<2880, 128>>>(eeg, emg, cmc);

    dim3 g2(NB, NG);
    k2_gat<<<g2, 128>>>(wpli_eeg, wpli_emg, a_eeg, a_emg, b_cmc,
                        g0w1, g0b1, g0w2, g0b2);

    k3_head<<<NB, 256>>>(g1w1, g1b1, g1w2, g1b2,
                         mlp0w, mlp0b, mlp1w, mlp1b, mlp2w, mlp2b,
                         bng, bnb, (float*)d_out);
}